// round 5
// baseline (speedup 1.0000x reference)
#include <cuda_runtime.h>
#include <cuda_bf16.h>
#include <math.h>

#define D 384
#define KK 16
#define TILE 64
#define TPB 512
#define ROW_PAD 388   // 384 + 4 floats padding; row stride 1552B (16B aligned)
#define NMAX 100000

// ---- scratch accumulators (device globals: no allocation allowed) ----
__device__ float g_P[KK * D];   // P = A^T F   (row-major [k][d])
__device__ float g_cs[KK];      // cluster sizes
__device__ float g_m[KK];       // m = A^T degrees = sum_e w_e * a[dst]
__device__ float g_S1;          // sum_e w_e * dot(a[src], a[dst])
__device__ float g_ne;          // number_of_edges = sum_e w_e
__device__ __nv_bfloat16 g_A16[NMAX * KK];   // bf16 assignment table (3.2MB, L2-resident)

// ------------------------------------------------------------------
__global__ void k_zero()
{
    int i = blockIdx.x * blockDim.x + threadIdx.x;
    if (i < KK * D) g_P[i] = 0.0f;
    if (i < KK) { g_cs[i] = 0.0f; g_m[i] = 0.0f; }
    if (i == 0) { g_S1 = 0.0f; g_ne = 0.0f; }
}

// ------------------------------------------------------------------
// Kernel A: per 64-row tile:
//   logits = F W + b -> softmax -> assignments (fp32 out + bf16 table + smem)
//   cluster_sizes in registers; P += A_tile^T F_tile in registers.
// W staged as k-major float4 quads: s_W4[dq*16+k] = W[4dq..4dq+3][k]
//   -> lane-k LDS.128 is bank-conflict-free (words 4k..4k+3 cover 32 banks/phase).
extern __shared__ float smem[];

__global__ __launch_bounds__(TPB) void k_assign(
    const float* __restrict__ F, const float* __restrict__ W,
    const float* __restrict__ b, float* __restrict__ a_out, int N)
{
    float* s_f  = smem;                        // TILE * ROW_PAD
    float* s_W4 = s_f + TILE * ROW_PAD;        // 96*16 float4 = 6144 floats
    float* s_a  = s_W4 + (D / 4) * KK * 4;     // TILE * KK
    float* s_cs = s_a + TILE * KK;             // KK (end-of-kernel flush only)

    const int t = threadIdx.x;

    // stage W as k-major float4 quads (one-time; gmem reads are small)
    for (int i = t; i < (D / 4) * KK; i += TPB) {
        int dq_ = i / KK, k_ = i % KK;
        float4 v;
        v.x = W[(4 * dq_ + 0) * KK + k_];
        v.y = W[(4 * dq_ + 1) * KK + k_];
        v.z = W[(4 * dq_ + 2) * KK + k_];
        v.w = W[(4 * dq_ + 3) * KK + k_];
        *(float4*)(s_W4 + (size_t)i * 4) = v;
    }
    if (t < KK) s_cs[t] = 0.0f;

    const int lane = t & 31;
    const int wrp  = t >> 5;          // 0..15
    const int k    = lane & 15;       // cluster index for GEMM phase
    const int s    = lane >> 4;       // row-pair selector (0/1)
    const float bk = b[k];
    float csacc = 0.0f;               // running cluster-size partial for cluster k

    // P-phase ownership: 384 active threads; thread owns d-quad dq (0..95),
    // k-quad kq (0..3):  pacc[j*4+c] accumulates a[i][kq*4+j]*f[i][dq*4+c]
    const bool p_act = (t < 384);
    const int dq = t % 96;
    const int kq = t / 96;
    float pacc[16];
    #pragma unroll
    for (int i = 0; i < 16; i++) pacc[i] = 0.0f;

    __syncthreads();

    const int NT = (N + TILE - 1) / TILE;
    for (int tile = blockIdx.x; tile < NT; tile += gridDim.x) {
        const int base   = tile * TILE;
        const int rows_n = min(TILE, N - base);

        // ---- stage feature tile (coalesced float4, zero-fill tail rows) ----
        const float4* F4 = (const float4*)(F + (size_t)base * D);
        for (int i = t; i < TILE * (D / 4); i += TPB) {
            int r = i / (D / 4);
            int c = i % (D / 4);
            float4 v = make_float4(0.f, 0.f, 0.f, 0.f);
            if (r < rows_n) v = F4[r * (D / 4) + c];
            *(float4*)(s_f + r * ROW_PAD + c * 4) = v;
        }
        __syncthreads();

        // ---- GEMM phase: warp handles rows wrp*4 + 2s + {0,1} ----
        const int r0 = wrp * 4 + s * 2;
        const int r1 = r0 + 1;
        float acc0 = bk, acc1 = bk;
        {
            const float4* wq = (const float4*)s_W4 + k;          // stride 16 float4s
            const float4* f0 = (const float4*)(s_f + r0 * ROW_PAD);
            const float4* f1 = (const float4*)(s_f + r1 * ROW_PAD);
            #pragma unroll 8
            for (int j = 0; j < D / 4; j++) {
                float4 wv = wq[j * 16];
                float4 x  = f0[j];
                float4 y  = f1[j];
                acc0 += wv.x * x.x + wv.y * x.y + wv.z * x.z + wv.w * x.w;
                acc1 += wv.x * y.x + wv.y * y.y + wv.z * y.z + wv.w * y.w;
            }
        }

        // ---- softmax over 16 clusters (within 16-lane groups) ----
        float a0, a1;
        {
            float mx = fmaxf(acc0, acc1);
            #pragma unroll
            for (int o = 1; o < 16; o <<= 1) mx = fmaxf(mx, __shfl_xor_sync(0xffffffffu, mx, o));
            float e0 = __expf(acc0 - mx);
            float e1 = __expf(acc1 - mx);
            float sm0 = e0, sm1 = e1;
            #pragma unroll
            for (int o = 1; o < 16; o <<= 1) {
                sm0 += __shfl_xor_sync(0xffffffffu, sm0, o);
                sm1 += __shfl_xor_sync(0xffffffffu, sm1, o);
            }
            a0 = e0 / sm0;
            a1 = e1 / sm1;
        }

        const bool v0 = (r0 < rows_n);
        const bool v1 = (r1 < rows_n);
        if (v0) {
            a_out[(size_t)(base + r0) * KK + k] = a0;
            g_A16[(size_t)(base + r0) * KK + k] = __float2bfloat16_rn(a0);
            s_a[r0 * KK + k] = a0;
            csacc += a0;
        }
        if (v1) {
            a_out[(size_t)(base + r1) * KK + k] = a1;
            g_A16[(size_t)(base + r1) * KK + k] = __float2bfloat16_rn(a1);
            s_a[r1 * KK + k] = a1;
            csacc += a1;
        }

        __syncthreads();  // s_a visible to all

        // ---- P phase: one LDS.128 (f, conflict-free) + one LDS.128 (a, broadcast) per row ----
        if (p_act) {
            const float* fp = s_f + dq * 4;
            const float* ap = s_a + kq * 4;
            for (int i = 0; i < rows_n; i++) {
                float4 fv = *(const float4*)(fp + i * ROW_PAD);
                float4 av = *(const float4*)(ap + i * KK);
                pacc[0]  += av.x * fv.x; pacc[1]  += av.x * fv.y; pacc[2]  += av.x * fv.z; pacc[3]  += av.x * fv.w;
                pacc[4]  += av.y * fv.x; pacc[5]  += av.y * fv.y; pacc[6]  += av.y * fv.z; pacc[7]  += av.y * fv.w;
                pacc[8]  += av.z * fv.x; pacc[9]  += av.z * fv.y; pacc[10] += av.z * fv.z; pacc[11] += av.z * fv.w;
                pacc[12] += av.w * fv.x; pacc[13] += av.w * fv.y; pacc[14] += av.w * fv.z; pacc[15] += av.w * fv.w;
            }
        }
        __syncthreads();  // before next tile overwrites s_f / s_a
    }

    // ---- flush cluster sizes: fold s=1 half onto s=0, then one smem atomic per lane<16 ----
    csacc += __shfl_xor_sync(0xffffffffu, csacc, 16);
    if (lane < 16) atomicAdd(&s_cs[k], csacc);

    // ---- flush P (spread-address global reductions, once per kernel) ----
    if (p_act) {
        #pragma unroll
        for (int j = 0; j < 4; j++) {
            #pragma unroll
            for (int c = 0; c < 4; c++) {
                atomicAdd(&g_P[(kq * 4 + j) * D + (dq * 4 + c)], pacc[j * 4 + c]);
            }
        }
    }
    __syncthreads();
    if (t < KK) atomicAdd(&g_cs[t], s_cs[t]);
}

// ------------------------------------------------------------------
// Kernel B: edge pass over bf16 assignment table (32B rows).
//   4-lane group per edge; lane sub owns 8B (4 bf16) of each row.
//   S1 += w * dot(a[src], a[dst]);  ne += w;  m[k] += w * a[dst][k]
__global__ __launch_bounds__(256) void k_edges(
    const int* __restrict__ es, const int* __restrict__ ed,
    const float* __restrict__ ew, int E)
{
    __shared__ float s_m[KK];
    __shared__ float s_s1, s_ne;
    const int t = threadIdx.x;
    if (t < KK) s_m[t] = 0.0f;
    if (t == 0) { s_s1 = 0.0f; s_ne = 0.0f; }
    __syncthreads();

    const int lane = t & 31;
    const int sub  = lane & 3;                          // 8B chunk within 32B row
    const int g0   = blockIdx.x * (blockDim.x >> 2) + (t >> 2);
    const int G    = gridDim.x * (blockDim.x >> 2);

    float lm0 = 0.f, lm1 = 0.f, lm2 = 0.f, lm3 = 0.f;   // k = sub*4 + {0..3}
    float ls1 = 0.f, lne = 0.f;

    const uint2* A2 = (const uint2*)g_A16;              // 4 uint2 per row
    for (int e = g0; e < E; e += G) {
        int sn = es[e], dn = ed[e];
        float wv = ew[e];
        uint2 xb = A2[(size_t)sn * 4 + sub];
        uint2 yb = A2[(size_t)dn * 4 + sub];
        float2 x0 = __bfloat1622float2(*(const __nv_bfloat162*)&xb.x);
        float2 x1 = __bfloat1622float2(*(const __nv_bfloat162*)&xb.y);
        float2 y0 = __bfloat1622float2(*(const __nv_bfloat162*)&yb.x);
        float2 y1 = __bfloat1622float2(*(const __nv_bfloat162*)&yb.y);
        float dot = x0.x * y0.x + x0.y * y0.y + x1.x * y1.x + x1.y * y1.y;
        dot += __shfl_xor_sync(0xffffffffu, dot, 1);
        dot += __shfl_xor_sync(0xffffffffu, dot, 2);
        if (sub == 0) { ls1 += wv * dot; lne += wv; }
        lm0 += wv * y0.x; lm1 += wv * y0.y; lm2 += wv * y1.x; lm3 += wv * y1.y;
    }

    // reduce lm across the 8 groups of the warp (lanes sharing sub)
    #pragma unroll
    for (int o = 4; o <= 16; o <<= 1) {
        lm0 += __shfl_xor_sync(0xffffffffu, lm0, o);
        lm1 += __shfl_xor_sync(0xffffffffu, lm1, o);
        lm2 += __shfl_xor_sync(0xffffffffu, lm2, o);
        lm3 += __shfl_xor_sync(0xffffffffu, lm3, o);
    }
    // full warp reduce for scalars (non-sub0 lanes contribute 0)
    #pragma unroll
    for (int o = 16; o > 0; o >>= 1) {
        ls1 += __shfl_xor_sync(0xffffffffu, ls1, o);
        lne += __shfl_xor_sync(0xffffffffu, lne, o);
    }
    if (lane < 4) {
        atomicAdd(&s_m[lane * 4 + 0], lm0);
        atomicAdd(&s_m[lane * 4 + 1], lm1);
        atomicAdd(&s_m[lane * 4 + 2], lm2);
        atomicAdd(&s_m[lane * 4 + 3], lm3);
    }
    if (lane == 0) { atomicAdd(&s_s1, ls1); atomicAdd(&s_ne, lne); }
    __syncthreads();
    if (t < KK) atomicAdd(&g_m[t], s_m[t]);
    if (t == 0) { atomicAdd(&g_S1, s_s1); atomicAdd(&g_ne, s_ne); }
}

// ------------------------------------------------------------------
// Kernel C: losses + features_pooled = selu(P / cs)
__global__ void k_final(float* __restrict__ out, int N)
{
    const int gi = blockIdx.x * blockDim.x + threadIdx.x;
    if (gi == 0) {
        float ne = g_ne;
        float msum = 0.0f, csq = 0.0f;
        #pragma unroll
        for (int kk2 = 0; kk2 < KK; kk2++) {
            msum += g_m[kk2] * g_m[kk2];
            csq  += g_cs[kk2] * g_cs[kk2];
        }
        float spectral = -(g_S1 - msum / (2.0f * ne)) / (2.0f * ne);
        float collapse = 0.1f * (sqrtf(csq) / (float)N * 4.0f - 1.0f);  // sqrt(K)=4
        size_t off = (size_t)KK * D + (size_t)N * KK;
        out[off]     = spectral;
        out[off + 1] = collapse;
    }
    if (gi < KK * D) {
        int kk2 = gi / D;
        float x = g_P[gi] / g_cs[kk2];
        const float alpha = 1.6732632423543772f;
        const float scale = 1.0507009873554805f;
        out[gi] = (x > 0.0f) ? scale * x : scale * alpha * expm1f(x);
    }
}

// ------------------------------------------------------------------
extern "C" void kernel_launch(void* const* d_in, const int* in_sizes, int n_in,
                              void* d_out, int out_size)
{
    const float* F  = (const float*)d_in[0];
    const int*   es = (const int*)d_in[1];
    const int*   ed = (const int*)d_in[2];
    const float* ew = (const float*)d_in[3];
    const float* W  = (const float*)d_in[4];
    const float* b  = (const float*)d_in[5];
    const int N = in_sizes[0] / D;
    const int E = in_sizes[1];

    float* out   = (float*)d_out;
    float* a_out = out + KK * D;   // assignments live right after features_pooled

    size_t smem_bytes = (size_t)(TILE * ROW_PAD + (D / 4) * KK * 4 + TILE * KK + KK) * sizeof(float);
    cudaFuncSetAttribute(k_assign, cudaFuncAttributeMaxDynamicSharedMemorySize, (int)smem_bytes);

    k_zero<<<13, 512>>>();
    k_assign<<<148, TPB, smem_bytes>>>(F, W, b, a_out, N);
    k_edges<<<1184, 256>>>(es, ed, ew, E);
    k_final<<<13, 512>>>(out, N);
}